// round 12
// baseline (speedup 1.0000x reference)
#include <cuda_runtime.h>
#include <cuda_fp16.h>
#include <cstdint>
#include <math.h>

#define BATCH 4
#define SEQ   2048
#define DIMS  1024
#define MTOT  (BATCH*SEQ)
#define NX    (MTOT*DIMS)
#define NWW   (DIMS*DIMS)

// Scratch (no cudaMalloc allowed)
__device__ __half g_xh[NX],   g_xl[NX];
__device__ __half g_wvh[NWW];
__device__ __half g_wqTh[NWW], g_wqTl[NWW];   // Wq^T [d][e]
__device__ __half g_wkTh[NWW], g_wkTl[NWW];   // Wk^T [d][e]
__device__ __half g_mth[NWW],  g_mtl[NWW];    // G^T = Wk^T*Wq  [d'][d]
__device__ __half g_th[NX],    g_tl[NX];      // T = X*G^T      [s][d']
__device__ __half g_vTh[NX];                  // V transposed   [b][e][s]
__device__ float  g_p[(size_t)BATCH * SEQ * SEQ];
__device__ __half g_ph[(size_t)BATCH * SEQ * SEQ];

#define BM 128
#define BN 128
#define BK 32                      // halves per K chunk (64B of data per row)
#define NSTAGE  3

// A tile (3-prod): 64B rows + XOR swizzle (2-way ldsm conflict, compact)
#define TILE_SW 8192u
// padded-pitch tile: 80B rows -> conflict-free ldmatrix (banks 20r+4c partition)
#define PITCH   80u
#define TILE_P  (128u * PITCH)     // 10240

// 3-prod stage: Ah,Al @SW + Bh,Bl @pitch = 36864;  1-prod: Ah,Bh @pitch = 20480
#define SM_P3 (NSTAGE * (2u * TILE_SW + 2u * TILE_P))   // 110592
#define SM_P1 (NSTAGE * (2u * TILE_P))                  // 61440

// swizzle for 64B-row tiles
#define SW(o) ((o) ^ ((((o) >> 7) & 3u) << 4))

// ---------------------------------------------------------------------------
// PTX helpers
// ---------------------------------------------------------------------------
__device__ __forceinline__ uint32_t smem_u32(const void* p) {
    uint32_t a;
    asm("{ .reg .u64 t; cvta.to.shared.u64 t, %1; cvt.u32.u64 %0, t; }"
        : "=r"(a) : "l"(p));
    return a;
}
__device__ __forceinline__ void cp16(uint32_t dst, const void* src) {
    asm volatile("cp.async.cg.shared.global [%0], [%1], 16;" :: "r"(dst), "l"(src));
}
#define CP_COMMIT()  asm volatile("cp.async.commit_group;" ::: "memory")
#define CP_WAIT(n)   asm volatile("cp.async.wait_group %0;" :: "n"(n) : "memory")

__device__ __forceinline__ void ldmx4(uint32_t* r, uint32_t addr) {
    asm volatile("ldmatrix.sync.aligned.m8n8.x4.shared.b16 {%0,%1,%2,%3}, [%4];"
                 : "=r"(r[0]), "=r"(r[1]), "=r"(r[2]), "=r"(r[3]) : "r"(addr));
}
__device__ __forceinline__ void mma16816(float* c, const uint32_t* a,
                                         uint32_t b0, uint32_t b1) {
    asm volatile(
        "mma.sync.aligned.m16n8k16.row.col.f32.f16.f16.f32 "
        "{%0,%1,%2,%3}, {%4,%5,%6,%7}, {%8,%9}, {%0,%1,%2,%3};"
        : "+f"(c[0]), "+f"(c[1]), "+f"(c[2]), "+f"(c[3])
        : "r"(a[0]), "r"(a[1]), "r"(a[2]), "r"(a[3]), "r"(b0), "r"(b1));
}

__device__ __forceinline__ void split_h(float v, __half& hi, __half& lo) {
    hi = __float2half_rn(v);
    lo = __float2half_rn(v - __half2float(hi));
}

// ---------------------------------------------------------------------------
// f16-split NT mainloop.
// NPROD=3: ah*bh + ah*bl + al*bh   (A tiles @SW64, B tiles @pitch80)
// NPROD=1: ah*bh                   (A and B tiles @pitch80, conflict-free)
// 8 warps: 4(M) x 2(N); warp tile 32x64. 3-stage cp.async pipeline, 1 sync.
// ---------------------------------------------------------------------------
template<int NPROD>
__device__ __forceinline__ void f16_mma_nt(
    const __half* __restrict__ Ah, const __half* __restrict__ Al, int lda,
    const __half* __restrict__ Bh, const __half* __restrict__ Bl, int ldb, int K,
    char* smem, float acc[2][8][4])
{
    constexpr bool USE_AL = (NPROD == 3);
    constexpr bool USE_BL = (NPROD >= 2);
    constexpr bool A_SW   = USE_AL;
    constexpr uint32_t TA   = A_SW ? TILE_SW : TILE_P;
    constexpr uint32_t OFFB = (USE_AL ? 2u : 1u) * TA;
    constexpr uint32_t OFFBL= OFFB + TILE_P;
    constexpr uint32_t STG  = OFFB + (USE_BL ? 2u : 1u) * TILE_P;

    const int tid = threadIdx.x;
    const int wid = tid >> 5, lane = tid & 31;
    const int wm = (wid & 3) * 32;
    const int wn = (wid >> 2) * 64;
    const int mat = lane >> 3, rw = lane & 7;
    const uint32_t sb = smem_u32(smem);
    const int nch = K / BK;

    auto aoff = [](uint32_t row, uint32_t cb) -> uint32_t {
        return A_SW ? SW(row * 64 + cb) : row * PITCH + cb;
    };

    auto load_chunk = [&](int ck, int st) {
        const int k0 = ck * BK;
        const uint32_t base = sb + (uint32_t)st * STG;
        #pragma unroll
        for (int j = 0; j < 2; j++) {
            int c = tid + j * 256;          // 0..511
            uint32_t r = (uint32_t)(c >> 2), i = (uint32_t)(c & 3);
            uint32_t ao = aoff(r, i * 16);
            cp16(base + ao, Ah + (size_t)r * lda + k0 + i * 8);
            if (USE_AL)
                cp16(base + TA + ao, Al + (size_t)r * lda + k0 + i * 8);
            uint32_t bo = r * PITCH + i * 16;
            cp16(base + OFFB + bo, Bh + (size_t)r * ldb + k0 + i * 8);
            if (USE_BL)
                cp16(base + OFFBL + bo, Bl + (size_t)r * ldb + k0 + i * 8);
        }
        CP_COMMIT();
    };

    load_chunk(0, 0);
    load_chunk(1, 1);

    int st = 0;
    for (int ck = 0; ck < nch; ck++) {
        if (ck + 1 < nch) { CP_WAIT(1); } else { CP_WAIT(0); }
        __syncthreads();

        if (ck + 2 < nch) {
            int s2 = st + 2; if (s2 >= NSTAGE) s2 -= NSTAGE;
            load_chunk(ck + 2, s2);
        }

        const uint32_t tb = sb + (uint32_t)st * STG;

        #pragma unroll
        for (int ks = 0; ks < BK; ks += 16) {
            uint32_t ah[2][4], al[2][4];
            #pragma unroll
            for (int mf = 0; mf < 2; mf++) {
                uint32_t row = (uint32_t)(wm + mf * 16 + (mat & 1) * 8 + rw);
                uint32_t cb  = (uint32_t)((ks + (mat >> 1) * 8) * 2);
                uint32_t off = aoff(row, cb);
                ldmx4(ah[mf], tb + off);
                if (USE_AL) ldmx4(al[mf], tb + TA + off);
            }
            #pragma unroll
            for (int p = 0; p < 4; p++) {
                uint32_t row = (uint32_t)(wn + p * 16 + ((mat >> 1) & 1) * 8 + rw);
                uint32_t cb  = (uint32_t)((ks + (mat & 1) * 8) * 2);
                uint32_t off = row * PITCH + cb;
                uint32_t bh[4], bl[4];
                ldmx4(bh, tb + OFFB + off);
                if (USE_BL) ldmx4(bl, tb + OFFBL + off);
                #pragma unroll
                for (int q = 0; q < 2; q++) {
                    const int nf = 2 * p + q;
                    #pragma unroll
                    for (int mf = 0; mf < 2; mf++) {
                        mma16816(acc[mf][nf], ah[mf], bh[2*q], bh[2*q+1]);
                        if (USE_BL)
                            mma16816(acc[mf][nf], ah[mf], bl[2*q], bl[2*q+1]);
                        if (USE_AL)
                            mma16816(acc[mf][nf], al[mf], bh[2*q], bh[2*q+1]);
                    }
                }
            }
        }
        if (++st >= NSTAGE) st = 0;
    }
    __syncthreads();
}

// fp32 epilogue: acc -> C row-major
__device__ __forceinline__ void epi_store(const float acc[2][8][4],
                                          float* __restrict__ C, int ldc)
{
    const int wid = threadIdx.x >> 5, lane = threadIdx.x & 31;
    const int wm = (wid & 3) * 32, wn = (wid >> 2) * 64;
    const int g = lane >> 2, t = lane & 3;
    #pragma unroll
    for (int mf = 0; mf < 2; mf++) {
        #pragma unroll
        for (int nf = 0; nf < 8; nf++) {
            const float* c = acc[mf][nf];
            float* p0 = C + (size_t)(wm + mf * 16 + g) * ldc + wn + nf * 8 + 2 * t;
            float* p1 = p0 + 8 * ldc;
            p0[0] = c[0]; p0[1] = c[1];
            p1[0] = c[2]; p1[1] = c[3];
        }
    }
}

// split-half epilogue: acc -> (Ch, Cl) row-major half planes
__device__ __forceinline__ void epi_store_split(const float acc[2][8][4],
                                                __half* __restrict__ Ch,
                                                __half* __restrict__ Cl, int ldc)
{
    const int wid = threadIdx.x >> 5, lane = threadIdx.x & 31;
    const int wm = (wid & 3) * 32, wn = (wid >> 2) * 64;
    const int g = lane >> 2, t = lane & 3;
    #pragma unroll
    for (int mf = 0; mf < 2; mf++) {
        #pragma unroll
        for (int nf = 0; nf < 8; nf++) {
            const float* c = acc[mf][nf];
            #pragma unroll
            for (int hh = 0; hh < 2; hh++) {
                size_t o = (size_t)(wm + mf * 16 + g + hh * 8) * ldc + wn + nf * 8 + 2 * t;
                __half2 h, l;
                split_h(c[hh*2+0], h.x, l.x);
                split_h(c[hh*2+1], h.y, l.y);
                *reinterpret_cast<__half2*>(Ch + o) = h;
                *reinterpret_cast<__half2*>(Cl + o) = l;
            }
        }
    }
}

// ---------------------------------------------------------------------------
// Kernel 0a: split X (hi/lo) and Wv (hi only)
// ---------------------------------------------------------------------------
__global__ void __launch_bounds__(256)
split_kernel(const float* __restrict__ X, const float* __restrict__ Wv)
{
    size_t i = ((size_t)blockIdx.x * 256 + threadIdx.x) * 2;
    if (i < NX) {
        float2 v = *reinterpret_cast<const float2*>(X + i);
        __half2 h, l;
        split_h(v.x, h.x, l.x);
        split_h(v.y, h.y, l.y);
        *reinterpret_cast<__half2*>(g_xh + i) = h;
        *reinterpret_cast<__half2*>(g_xl + i) = l;
    } else {
        size_t j = i - NX;
        float2 v = *reinterpret_cast<const float2*>(Wv + j);
        __half2 h;
        h.x = __float2half_rn(v.x);
        h.y = __float2half_rn(v.y);
        *reinterpret_cast<__half2*>(g_wvh + j) = h;
    }
}

// ---------------------------------------------------------------------------
// Kernel 0b: tiled transpose + split of Wq, Wk  ->  WqT/WkT half planes
// ---------------------------------------------------------------------------
__global__ void __launch_bounds__(256)
wtrans_kernel(const float* __restrict__ Wq, const float* __restrict__ Wk)
{
    __shared__ float tile[32][33];
    const float* W = blockIdx.z ? Wk : Wq;
    __half* dh = blockIdx.z ? g_wkTh : g_wqTh;
    __half* dl = blockIdx.z ? g_wkTl : g_wqTl;
    const int tx = threadIdx.x & 31, ty = threadIdx.x >> 5;   // 32 x 8
    const int d0 = blockIdx.x * 32;
    const int e0 = blockIdx.y * 32;

    #pragma unroll
    for (int j = ty; j < 32; j += 8)
        tile[j][tx] = W[(size_t)(e0 + j) * DIMS + d0 + tx];
    __syncthreads();

    #pragma unroll
    for (int j = ty; j < 32; j += 8) {
        float v = tile[tx][j];
        __half h, l;
        split_h(v, h, l);
        size_t o = (size_t)(d0 + j) * DIMS + e0 + tx;
        dh[o] = h;
        dl[o] = l;
    }
}

// ---------------------------------------------------------------------------
// Kernel 1: G^T = Wk^T * Wq  (NT on transposed weights), split-half out
// ---------------------------------------------------------------------------
__global__ void __launch_bounds__(256, 2)
mt_kernel()
{
    extern __shared__ char smem[];
    const int bn = blockIdx.x, bm = blockIdx.y;

    float acc[2][8][4] = {};
    f16_mma_nt<3>(g_wkTh + (size_t)bm * BM * DIMS, g_wkTl + (size_t)bm * BM * DIMS, DIMS,
                  g_wqTh + (size_t)bn * BN * DIMS, g_wqTl + (size_t)bn * BN * DIMS, DIMS,
                  DIMS, smem, acc);
    epi_store_split(acc, g_mth + (size_t)bm * BM * DIMS + bn * BN,
                         g_mtl + (size_t)bm * BM * DIMS + bn * BN, DIMS);
}

// ---------------------------------------------------------------------------
// Kernel 2: T = X * G^T (3-prod, split out) and V = X * Wv^T (1-prod,
// transposed hi-only out via smem-staged coalesced store)
// grid.x: [0,8) -> T, [8,16) -> V
// ---------------------------------------------------------------------------
#define VS_PITCH 136   // halves per row of the staging tile (pad vs 128)

__global__ void __launch_bounds__(256, 2)
tv_kernel()
{
    extern __shared__ char smem[];
    const int bn = blockIdx.x, bm = blockIdx.y;
    const int which = bn >> 3, nc = bn & 7;

    float acc[2][8][4] = {};

    if (which == 0) {
        f16_mma_nt<3>(g_xh + (size_t)bm * BM * DIMS, g_xl + (size_t)bm * BM * DIMS, DIMS,
                      g_mth + (size_t)nc * BN * DIMS, g_mtl + (size_t)nc * BN * DIMS, DIMS,
                      DIMS, smem, acc);
        epi_store_split(acc, g_th + (size_t)bm * BM * DIMS + nc * BN,
                             g_tl + (size_t)bm * BM * DIMS + nc * BN, DIMS);
    } else {
        f16_mma_nt<1>(g_xh + (size_t)bm * BM * DIMS, (const __half*)nullptr, DIMS,
                      g_wvh + (size_t)nc * BN * DIMS, (const __half*)nullptr, DIMS,
                      DIMS, smem, acc);

        // stage transposed tile in smem: vs[e_local][s_local], then coalesced out
        __half* vs = reinterpret_cast<__half*>(smem);
        const int wid = threadIdx.x >> 5, lane = threadIdx.x & 31;
        const int wm = (wid & 3) * 32, wn = (wid >> 2) * 64;
        const int g = lane >> 2, t = lane & 3;
        #pragma unroll
        for (int mf = 0; mf < 2; mf++) {
            #pragma unroll
            for (int nf = 0; nf < 8; nf++) {
                const float* c = acc[mf][nf];
                #pragma unroll
                for (int hh = 0; hh < 2; hh++) {
                    int s_local = wm + mf * 16 + g + hh * 8;
                    int e_local = wn + nf * 8 + 2 * t;
                    vs[(size_t)e_local * VS_PITCH + s_local]       = __float2half_rn(c[hh*2+0]);
                    vs[(size_t)(e_local + 1) * VS_PITCH + s_local] = __float2half_rn(c[hh*2+1]);
                }
            }
        }
        __syncthreads();

        const int m0 = bm * BM;
        const int b = m0 / SEQ, s0 = m0 % SEQ;
        __half* dst = g_vTh + (size_t)b * DIMS * SEQ + (size_t)(nc * BN) * SEQ + s0;
        const int tid = threadIdx.x;
        #pragma unroll
        for (int j = 0; j < 8; j++) {
            int idx = tid + j * 256;
            int row = idx >> 4, c16 = idx & 15;
            uint4 v = *reinterpret_cast<const uint4*>(vs + (size_t)row * VS_PITCH + c16 * 8);
            *reinterpret_cast<uint4*>(dst + (size_t)row * SEQ + c16 * 8) = v;
        }
    }
}

// ---------------------------------------------------------------------------
// Kernel 3: scores S = T X^T, lower-triangle-packed grid, fp32 out
// ---------------------------------------------------------------------------
#define NQT (SEQ / BM)                       // 16
#define NTRI (NQT * (NQT + 1) / 2)           // 136

__global__ void __launch_bounds__(256, 2)
scores_kernel()
{
    // decode lower-triangle linear index -> (qt, kt)
    int idx = blockIdx.x;
    int qt = 0;
    while ((qt + 1) * (qt + 2) / 2 <= idx) qt++;
    const int kt = idx - qt * (qt + 1) / 2;
    const int b = blockIdx.z;

    extern __shared__ char smem[];
    const size_t ao = ((size_t)b * SEQ + qt * BM) * DIMS;
    const size_t bo = ((size_t)b * SEQ + kt * BN) * DIMS;

    float acc[2][8][4] = {};
    f16_mma_nt<3>(g_th + ao, g_tl + ao, DIMS, g_xh + bo, g_xl + bo, DIMS,
                  DIMS, smem, acc);
    epi_store(acc, g_p + (size_t)b * SEQ * SEQ + (size_t)(qt * BM) * SEQ + kt * BN, SEQ);
}

// ---------------------------------------------------------------------------
// Kernel 4: causal row softmax; emits hi-half P only (zeros above diagonal)
// ---------------------------------------------------------------------------
__global__ void __launch_bounds__(256)
softmax_kernel()
{
    const int row = blockIdx.x;
    const int b = row / SEQ, i = row % SEQ;
    const size_t ro = (size_t)b * SEQ * SEQ + (size_t)i * SEQ;
    const float* s = g_p + ro;
    const int len = i + 1;
    const int tid = threadIdx.x;
    __shared__ float red[8];

    float m = -INFINITY;
    for (int j = tid; j < len; j += 256) m = fmaxf(m, s[j]);
    #pragma unroll
    for (int o = 16; o > 0; o >>= 1) m = fmaxf(m, __shfl_xor_sync(0xFFFFFFFFu, m, o));
    if ((tid & 31) == 0) red[tid >> 5] = m;
    __syncthreads();
    if (tid < 8) {
        float v = red[tid];
        #pragma unroll
        for (int o = 4; o > 0; o >>= 1) v = fmaxf(v, __shfl_xor_sync(0xFFu, v, o));
        if (tid == 0) red[0] = v;
    }
    __syncthreads();
    m = red[0];
    __syncthreads();

    float sum = 0.0f;
    for (int j = tid; j < len; j += 256) sum += __expf(s[j] - m);
    #pragma unroll
    for (int o = 16; o > 0; o >>= 1) sum += __shfl_xor_sync(0xFFFFFFFFu, sum, o);
    if ((tid & 31) == 0) red[tid >> 5] = sum;
    __syncthreads();
    if (tid < 8) {
        float v = red[tid];
        #pragma unroll
        for (int o = 4; o > 0; o >>= 1) v += __shfl_xor_sync(0xFFu, v, o);
        if (tid == 0) red[0] = v;
    }
    __syncthreads();
    const float inv = 1.0f / red[0];

    for (int j = tid; j < SEQ; j += 256) {
        float p = (j < len) ? __expf(s[j] - m) * inv : 0.0f;
        g_ph[ro + j] = __float2half_rn(p);
    }
}

// ---------------------------------------------------------------------------
// Kernel 5: O = P V  (1 product: ph*vh; K limited by causality)
// ---------------------------------------------------------------------------
__global__ void __launch_bounds__(256, 2)
av_kernel(float* __restrict__ Out)
{
    const int nt = blockIdx.x, qt = blockIdx.y, b = blockIdx.z;
    extern __shared__ char smem[];
    const size_t ao = (size_t)b * SEQ * SEQ + (size_t)(qt * BM) * SEQ;
    const size_t bo = (size_t)b * DIMS * SEQ + (size_t)(nt * BN) * SEQ;

    float acc[2][8][4] = {};
    f16_mma_nt<1>(g_ph + ao, (const __half*)nullptr, SEQ,
                  g_vTh + bo, (const __half*)nullptr, SEQ, (qt + 1) * BM, smem, acc);
    epi_store(acc, Out + ((size_t)b * SEQ + qt * BM) * DIMS + nt * BN, DIMS);
}

// ---------------------------------------------------------------------------
extern "C" void kernel_launch(void* const* d_in, const int* in_sizes, int n_in,
                              void* d_out, int out_size)
{
    const float* X  = (const float*)d_in[0];
    const float* Wq = (const float*)d_in[1];
    const float* Wk = (const float*)d_in[2];
    const float* Wv = (const float*)d_in[3];
    float* O = (float*)d_out;

    cudaFuncSetAttribute(mt_kernel,     cudaFuncAttributeMaxDynamicSharedMemorySize, SM_P3);
    cudaFuncSetAttribute(tv_kernel,     cudaFuncAttributeMaxDynamicSharedMemorySize, SM_P3);
    cudaFuncSetAttribute(scores_kernel, cudaFuncAttributeMaxDynamicSharedMemorySize, SM_P3);
    cudaFuncSetAttribute(av_kernel,     cudaFuncAttributeMaxDynamicSharedMemorySize, SM_P1);

    split_kernel<<<(NX + NWW) / 512, 256>>>(X, Wv);
    wtrans_kernel<<<dim3(DIMS / 32, DIMS / 32, 2), 256>>>(Wq, Wk);
    mt_kernel<<<dim3(DIMS / BN, DIMS / BM), 256, SM_P3>>>();
    tv_kernel<<<dim3(2 * (DIMS / BN), MTOT / BM), 256, SM_P3>>>();
    scores_kernel<<<dim3(NTRI, 1, BATCH), 256, SM_P3>>>();
    softmax_kernel<<<dim3(MTOT), 256>>>();
    av_kernel<<<dim3(DIMS / BN, SEQ / BM, BATCH), 256, SM_P1>>>(O);
}

// round 13
// speedup vs baseline: 1.1069x; 1.1069x over previous
#include <cuda_runtime.h>
#include <cuda_fp16.h>
#include <cstdint>
#include <math.h>

#define BATCH 4
#define SEQ   2048
#define DIMS  1024
#define MTOT  (BATCH*SEQ)
#define NX    (MTOT*DIMS)
#define NWW   (DIMS*DIMS)

// Scratch (no cudaMalloc allowed)
__device__ __half g_xh[NX],   g_xl[NX];
__device__ __half g_wvh[NWW];
__device__ __half g_wqTh[NWW], g_wqTl[NWW];   // Wq^T [d][e]
__device__ __half g_wkTh[NWW], g_wkTl[NWW];   // Wk^T [d][e]
__device__ __half g_mth[NWW],  g_mtl[NWW];    // G^T = Wk^T*Wq  [d'][d]
__device__ __half g_th[NX],    g_tl[NX];      // T = X*G^T      [s][d']
__device__ __half g_vTh[NX];                  // V transposed   [b][e][s]
__device__ float  g_p[(size_t)BATCH * SEQ * SEQ];
__device__ __half g_ph[(size_t)BATCH * SEQ * SEQ];

#define BM 128
#define BN 128
#define BK 32                      // halves per K chunk (64B rows)
#define TILE_B  8192u              // 128 rows * 64B
#define NSTAGE  3
#define SM_P3 (NSTAGE * 4 * TILE_B)   // 98304
#define SM_P1 (NSTAGE * 2 * TILE_B)   // 49152

// swizzle: XOR 16B-chunk index (bits 4-5) with (row>>1)&3 (bits 7-8)
#define SW(o) ((o) ^ ((((o) >> 7) & 3u) << 4))

// ---------------------------------------------------------------------------
// PTX helpers
// ---------------------------------------------------------------------------
__device__ __forceinline__ uint32_t smem_u32(const void* p) {
    uint32_t a;
    asm("{ .reg .u64 t; cvta.to.shared.u64 t, %1; cvt.u32.u64 %0, t; }"
        : "=r"(a) : "l"(p));
    return a;
}
__device__ __forceinline__ void cp16(uint32_t dst, const void* src) {
    asm volatile("cp.async.cg.shared.global [%0], [%1], 16;" :: "r"(dst), "l"(src));
}
#define CP_COMMIT()  asm volatile("cp.async.commit_group;" ::: "memory")
#define CP_WAIT(n)   asm volatile("cp.async.wait_group %0;" :: "n"(n) : "memory")

__device__ __forceinline__ void ldmx4(uint32_t* r, uint32_t addr) {
    asm volatile("ldmatrix.sync.aligned.m8n8.x4.shared.b16 {%0,%1,%2,%3}, [%4];"
                 : "=r"(r[0]), "=r"(r[1]), "=r"(r[2]), "=r"(r[3]) : "r"(addr));
}
__device__ __forceinline__ void mma16816(float* c, const uint32_t* a,
                                         uint32_t b0, uint32_t b1) {
    asm volatile(
        "mma.sync.aligned.m16n8k16.row.col.f32.f16.f16.f32 "
        "{%0,%1,%2,%3}, {%4,%5,%6,%7}, {%8,%9}, {%0,%1,%2,%3};"
        : "+f"(c[0]), "+f"(c[1]), "+f"(c[2]), "+f"(c[3])
        : "r"(a[0]), "r"(a[1]), "r"(a[2]), "r"(a[3]), "r"(b0), "r"(b1));
}

__device__ __forceinline__ void split_h(float v, __half& hi, __half& lo) {
    hi = __float2half_rn(v);
    lo = __float2half_rn(v - __half2float(hi));
}

// ---------------------------------------------------------------------------
// f16-split NT mainloop.
// NPROD=3: ah*bh + ah*bl + al*bh   (tiles Ah,Al,Bh,Bl)
// NPROD=1: ah*bh                   (tiles Ah,Bh)
// 8 warps: 4(M) x 2(N); warp tile 32x64. 3-stage cp.async pipeline, 1 sync.
// MMA issue is PRODUCT-MAJOR: same-accumulator reuse distance = 4 MMAs.
// ---------------------------------------------------------------------------
template<int NPROD>
__device__ __forceinline__ void f16_mma_nt(
    const __half* __restrict__ Ah, const __half* __restrict__ Al, int lda,
    const __half* __restrict__ Bh, const __half* __restrict__ Bl, int ldb, int K,
    char* smem, float acc[2][8][4])
{
    constexpr bool USE_AL = (NPROD == 3);
    constexpr bool USE_BL = (NPROD >= 2);
    constexpr uint32_t NT  = 1u + (USE_AL ? 1u : 0u) + 1u + (USE_BL ? 1u : 0u);
    constexpr uint32_t STG = NT * TILE_B;
    constexpr uint32_t TBH = (USE_AL ? 2u : 1u) * TILE_B;
    constexpr uint32_t TBL = TBH + TILE_B;

    const int tid = threadIdx.x;
    const int wid = tid >> 5, lane = tid & 31;
    const int wm = (wid & 3) * 32;
    const int wn = (wid >> 2) * 64;
    const int mat = lane >> 3, rw = lane & 7;
    const uint32_t sb = smem_u32(smem);
    const int nch = K / BK;

    auto load_chunk = [&](int ck, int st) {
        const int k0 = ck * BK;
        const uint32_t base = sb + (uint32_t)st * STG;
        #pragma unroll
        for (int j = 0; j < 2; j++) {
            int c = tid + j * 256;          // 0..511
            int r = c >> 2, i = c & 3;
            uint32_t sw = SW((uint32_t)(r * 64 + i * 16));
            cp16(base + sw, Ah + (size_t)r * lda + k0 + i * 8);
            if (USE_AL)
                cp16(base + TILE_B + sw, Al + (size_t)r * lda + k0 + i * 8);
            cp16(base + TBH + sw, Bh + (size_t)r * ldb + k0 + i * 8);
            if (USE_BL)
                cp16(base + TBL + sw, Bl + (size_t)r * ldb + k0 + i * 8);
        }
        CP_COMMIT();
    };

    load_chunk(0, 0);
    load_chunk(1, 1);

    int st = 0;
    for (int ck = 0; ck < nch; ck++) {
        if (ck + 1 < nch) { CP_WAIT(1); } else { CP_WAIT(0); }
        __syncthreads();

        if (ck + 2 < nch) {
            int s2 = st + 2; if (s2 >= NSTAGE) s2 -= NSTAGE;
            load_chunk(ck + 2, s2);
        }

        const uint32_t tb = sb + (uint32_t)st * STG;

        #pragma unroll
        for (int ks = 0; ks < BK; ks += 16) {
            uint32_t ah[2][4], al[2][4];
            #pragma unroll
            for (int mf = 0; mf < 2; mf++) {
                int row = wm + mf * 16 + (mat & 1) * 8 + rw;
                int col = ks + (mat >> 1) * 8;
                uint32_t off = SW((uint32_t)(row * 64 + col * 2));
                ldmx4(ah[mf], tb + off);
                if (USE_AL) ldmx4(al[mf], tb + TILE_B + off);
            }
            #pragma unroll
            for (int p = 0; p < 4; p++) {
                int row = wn + p * 16 + ((mat >> 1) & 1) * 8 + rw;
                int col = ks + (mat & 1) * 8;
                uint32_t off = SW((uint32_t)(row * 64 + col * 2));
                uint32_t bh[4], bl[4];
                ldmx4(bh, tb + TBH + off);
                if (USE_BL) ldmx4(bl, tb + TBL + off);

                // product-major: dependent reuse of each acc at distance 4
                #pragma unroll
                for (int q = 0; q < 2; q++)
                    #pragma unroll
                    for (int mf = 0; mf < 2; mf++)
                        mma16816(acc[mf][2*p+q], ah[mf], bh[2*q], bh[2*q+1]);
                if (USE_BL) {
                    #pragma unroll
                    for (int q = 0; q < 2; q++)
                        #pragma unroll
                        for (int mf = 0; mf < 2; mf++)
                            mma16816(acc[mf][2*p+q], ah[mf], bl[2*q], bl[2*q+1]);
                }
                if (USE_AL) {
                    #pragma unroll
                    for (int q = 0; q < 2; q++)
                        #pragma unroll
                        for (int mf = 0; mf < 2; mf++)
                            mma16816(acc[mf][2*p+q], al[mf], bh[2*q], bh[2*q+1]);
                }
            }
        }
        if (++st >= NSTAGE) st = 0;
    }
    __syncthreads();
}

// fp32 epilogue: acc -> C row-major
__device__ __forceinline__ void epi_store(const float acc[2][8][4],
                                          float* __restrict__ C, int ldc)
{
    const int wid = threadIdx.x >> 5, lane = threadIdx.x & 31;
    const int wm = (wid & 3) * 32, wn = (wid >> 2) * 64;
    const int g = lane >> 2, t = lane & 3;
    #pragma unroll
    for (int mf = 0; mf < 2; mf++) {
        #pragma unroll
        for (int nf = 0; nf < 8; nf++) {
            const float* c = acc[mf][nf];
            float* p0 = C + (size_t)(wm + mf * 16 + g) * ldc + wn + nf * 8 + 2 * t;
            float* p1 = p0 + 8 * ldc;
            p0[0] = c[0]; p0[1] = c[1];
            p1[0] = c[2]; p1[1] = c[3];
        }
    }
}

// split-half epilogue: acc -> (Ch, Cl) row-major half planes
__device__ __forceinline__ void epi_store_split(const float acc[2][8][4],
                                                __half* __restrict__ Ch,
                                                __half* __restrict__ Cl, int ldc)
{
    const int wid = threadIdx.x >> 5, lane = threadIdx.x & 31;
    const int wm = (wid & 3) * 32, wn = (wid >> 2) * 64;
    const int g = lane >> 2, t = lane & 3;
    #pragma unroll
    for (int mf = 0; mf < 2; mf++) {
        #pragma unroll
        for (int nf = 0; nf < 8; nf++) {
            const float* c = acc[mf][nf];
            #pragma unroll
            for (int hh = 0; hh < 2; hh++) {
                size_t o = (size_t)(wm + mf * 16 + g + hh * 8) * ldc + wn + nf * 8 + 2 * t;
                __half2 h, l;
                split_h(c[hh*2+0], h.x, l.x);
                split_h(c[hh*2+1], h.y, l.y);
                *reinterpret_cast<__half2*>(Ch + o) = h;
                *reinterpret_cast<__half2*>(Cl + o) = l;
            }
        }
    }
}

// ---------------------------------------------------------------------------
// Kernel 0a: split X (hi/lo) and Wv (hi only)
// ---------------------------------------------------------------------------
__global__ void __launch_bounds__(256)
split_kernel(const float* __restrict__ X, const float* __restrict__ Wv)
{
    size_t i = ((size_t)blockIdx.x * 256 + threadIdx.x) * 2;
    if (i < NX) {
        float2 v = *reinterpret_cast<const float2*>(X + i);
        __half2 h, l;
        split_h(v.x, h.x, l.x);
        split_h(v.y, h.y, l.y);
        *reinterpret_cast<__half2*>(g_xh + i) = h;
        *reinterpret_cast<__half2*>(g_xl + i) = l;
    } else {
        size_t j = i - NX;
        float2 v = *reinterpret_cast<const float2*>(Wv + j);
        __half2 h;
        h.x = __float2half_rn(v.x);
        h.y = __float2half_rn(v.y);
        *reinterpret_cast<__half2*>(g_wvh + j) = h;
    }
}

// ---------------------------------------------------------------------------
// Kernel 0b: tiled transpose + split of Wq, Wk  ->  WqT/WkT half planes
// ---------------------------------------------------------------------------
__global__ void __launch_bounds__(256)
wtrans_kernel(const float* __restrict__ Wq, const float* __restrict__ Wk)
{
    __shared__ float tile[32][33];
    const float* W = blockIdx.z ? Wk : Wq;
    __half* dh = blockIdx.z ? g_wkTh : g_wqTh;
    __half* dl = blockIdx.z ? g_wkTl : g_wqTl;
    const int tx = threadIdx.x & 31, ty = threadIdx.x >> 5;   // 32 x 8
    const int d0 = blockIdx.x * 32;
    const int e0 = blockIdx.y * 32;

    #pragma unroll
    for (int j = ty; j < 32; j += 8)
        tile[j][tx] = W[(size_t)(e0 + j) * DIMS + d0 + tx];
    __syncthreads();

    #pragma unroll
    for (int j = ty; j < 32; j += 8) {
        float v = tile[tx][j];
        __half h, l;
        split_h(v, h, l);
        size_t o = (size_t)(d0 + j) * DIMS + e0 + tx;
        dh[o] = h;
        dl[o] = l;
    }
}

// ---------------------------------------------------------------------------
// Kernel 1: G^T = Wk^T * Wq  (NT on transposed weights), split-half out
// ---------------------------------------------------------------------------
__global__ void __launch_bounds__(256, 2)
mt_kernel()
{
    extern __shared__ char smem[];
    const int bn = blockIdx.x, bm = blockIdx.y;

    float acc[2][8][4] = {};
    f16_mma_nt<3>(g_wkTh + (size_t)bm * BM * DIMS, g_wkTl + (size_t)bm * BM * DIMS, DIMS,
                  g_wqTh + (size_t)bn * BN * DIMS, g_wqTl + (size_t)bn * BN * DIMS, DIMS,
                  DIMS, smem, acc);
    epi_store_split(acc, g_mth + (size_t)bm * BM * DIMS + bn * BN,
                         g_mtl + (size_t)bm * BM * DIMS + bn * BN, DIMS);
}

// ---------------------------------------------------------------------------
// Kernel 2: T = X * G^T (3-prod, split out) and V = X * Wv^T (1-prod,
// transposed hi-only out via smem-staged coalesced store)
// grid.x: [0,8) -> T, [8,16) -> V
// ---------------------------------------------------------------------------
#define VS_PITCH 136   // halves per row of the staging tile (pad vs 128)

__global__ void __launch_bounds__(256, 2)
tv_kernel()
{
    extern __shared__ char smem[];
    const int bn = blockIdx.x, bm = blockIdx.y;
    const int which = bn >> 3, nc = bn & 7;

    float acc[2][8][4] = {};

    if (which == 0) {
        f16_mma_nt<3>(g_xh + (size_t)bm * BM * DIMS, g_xl + (size_t)bm * BM * DIMS, DIMS,
                      g_mth + (size_t)nc * BN * DIMS, g_mtl + (size_t)nc * BN * DIMS, DIMS,
                      DIMS, smem, acc);
        epi_store_split(acc, g_th + (size_t)bm * BM * DIMS + nc * BN,
                             g_tl + (size_t)bm * BM * DIMS + nc * BN, DIMS);
    } else {
        f16_mma_nt<1>(g_xh + (size_t)bm * BM * DIMS, (const __half*)nullptr, DIMS,
                      g_wvh + (size_t)nc * BN * DIMS, (const __half*)nullptr, DIMS,
                      DIMS, smem, acc);

        // stage transposed tile in smem: vs[e_local][s_local], then coalesced out
        __half* vs = reinterpret_cast<__half*>(smem);
        const int wid = threadIdx.x >> 5, lane = threadIdx.x & 31;
        const int wm = (wid & 3) * 32, wn = (wid >> 2) * 64;
        const int g = lane >> 2, t = lane & 3;
        #pragma unroll
        for (int mf = 0; mf < 2; mf++) {
            #pragma unroll
            for (int nf = 0; nf < 8; nf++) {
                const float* c = acc[mf][nf];
                #pragma unroll
                for (int hh = 0; hh < 2; hh++) {
                    int s_local = wm + mf * 16 + g + hh * 8;
                    int e_local = wn + nf * 8 + 2 * t;
                    vs[(size_t)e_local * VS_PITCH + s_local]       = __float2half_rn(c[hh*2+0]);
                    vs[(size_t)(e_local + 1) * VS_PITCH + s_local] = __float2half_rn(c[hh*2+1]);
                }
            }
        }
        __syncthreads();

        const int m0 = bm * BM;
        const int b = m0 / SEQ, s0 = m0 % SEQ;
        __half* dst = g_vTh + (size_t)b * DIMS * SEQ + (size_t)(nc * BN) * SEQ + s0;
        const int tid = threadIdx.x;
        #pragma unroll
        for (int j = 0; j < 8; j++) {
            int idx = tid + j * 256;
            int row = idx >> 4, c16 = idx & 15;
            uint4 v = *reinterpret_cast<const uint4*>(vs + (size_t)row * VS_PITCH + c16 * 8);
            *reinterpret_cast<uint4*>(dst + (size_t)row * SEQ + c16 * 8) = v;
        }
    }
}

// ---------------------------------------------------------------------------
// Kernel 3: scores S = T X^T, lower-triangle-packed grid, fp32 out
// ---------------------------------------------------------------------------
#define NQT (SEQ / BM)                       // 16
#define NTRI (NQT * (NQT + 1) / 2)           // 136

__global__ void __launch_bounds__(256, 2)
scores_kernel()
{
    // decode lower-triangle linear index -> (qt, kt)
    int idx = blockIdx.x;
    int qt = 0;
    while ((qt + 1) * (qt + 2) / 2 <= idx) qt++;
    const int kt = idx - qt * (qt + 1) / 2;
    const int b = blockIdx.z;

    extern __shared__ char smem[];
    const size_t ao = ((size_t)b * SEQ + qt * BM) * DIMS;
    const size_t bo = ((size_t)b * SEQ + kt * BN) * DIMS;

    float acc[2][8][4] = {};
    f16_mma_nt<3>(g_th + ao, g_tl + ao, DIMS, g_xh + bo, g_xl + bo, DIMS,
                  DIMS, smem, acc);
    epi_store(acc, g_p + (size_t)b * SEQ * SEQ + (size_t)(qt * BM) * SEQ + kt * BN, SEQ);
}

// ---------------------------------------------------------------------------
// Kernel 4: causal row softmax; emits hi-half P only (zeros above diagonal)
// ---------------------------------------------------------------------------
__global__ void __launch_bounds__(256)
softmax_kernel()
{
    const int row = blockIdx.x;
    const int b = row / SEQ, i = row % SEQ;
    const size_t ro = (size_t)b * SEQ * SEQ + (size_t)i * SEQ;
    const float* s = g_p + ro;
    const int len = i + 1;
    const int tid = threadIdx.x;
    __shared__ float red[8];

    float m = -INFINITY;
    for (int j = tid; j < len; j += 256) m = fmaxf(m, s[j]);
    #pragma unroll
    for (int o = 16; o > 0; o >>= 1) m = fmaxf(m, __shfl_xor_sync(0xFFFFFFFFu, m, o));
    if ((tid & 31) == 0) red[tid >> 5] = m;
    __syncthreads();
    if (tid < 8) {
        float v = red[tid];
        #pragma unroll
        for (int o = 4; o > 0; o >>= 1) v = fmaxf(v, __shfl_xor_sync(0xFFu, v, o));
        if (tid == 0) red[0] = v;
    }
    __syncthreads();
    m = red[0];
    __syncthreads();

    float sum = 0.0f;
    for (int j = tid; j < len; j += 256) sum += __expf(s[j] - m);
    #pragma unroll
    for (int o = 16; o > 0; o >>= 1) sum += __shfl_xor_sync(0xFFFFFFFFu, sum, o);
    if ((tid & 31) == 0) red[tid >> 5] = sum;
    __syncthreads();
    if (tid < 8) {
        float v = red[tid];
        #pragma unroll
        for (int o = 4; o > 0; o >>= 1) v += __shfl_xor_sync(0xFFu, v, o);
        if (tid == 0) red[0] = v;
    }
    __syncthreads();
    const float inv = 1.0f / red[0];

    for (int j = tid; j < SEQ; j += 256) {
        float p = (j < len) ? __expf(s[j] - m) * inv : 0.0f;
        g_ph[ro + j] = __float2half_rn(p);
    }
}

// ---------------------------------------------------------------------------
// Kernel 5: O = P V  (1 product: ph*vh; K limited by causality)
// ---------------------------------------------------------------------------
__global__ void __launch_bounds__(256, 2)
av_kernel(float* __restrict__ Out)
{
    const int nt = blockIdx.x, qt = blockIdx.y, b = blockIdx.z;
    extern __shared__ char smem[];
    const size_t ao = (size_t)b * SEQ * SEQ + (size_t)(qt * BM) * SEQ;
    const size_t bo = (size_t)b * DIMS * SEQ + (size_t)(nt * BN) * SEQ;

    float acc[2][8][4] = {};
    f16_mma_nt<1>(g_ph + ao, (const __half*)nullptr, SEQ,
                  g_vTh + bo, (const __half*)nullptr, SEQ, (qt + 1) * BM, smem, acc);
    epi_store(acc, Out + ((size_t)b * SEQ + qt * BM) * DIMS + nt * BN, DIMS);
}

// ---------------------------------------------------------------------------
extern "C" void kernel_launch(void* const* d_in, const int* in_sizes, int n_in,
                              void* d_out, int out_size)
{
    const float* X  = (const float*)d_in[0];
    const float* Wq = (const float*)d_in[1];
    const float* Wk = (const float*)d_in[2];
    const float* Wv = (const float*)d_in[3];
    float* O = (float*)d_out;

    cudaFuncSetAttribute(mt_kernel,     cudaFuncAttributeMaxDynamicSharedMemorySize, SM_P3);
    cudaFuncSetAttribute(tv_kernel,     cudaFuncAttributeMaxDynamicSharedMemorySize, SM_P3);
    cudaFuncSetAttribute(scores_kernel, cudaFuncAttributeMaxDynamicSharedMemorySize, SM_P3);
    cudaFuncSetAttribute(av_kernel,     cudaFuncAttributeMaxDynamicSharedMemorySize, SM_P1);

    split_kernel<<<(NX + NWW) / 512, 256>>>(X, Wv);
    wtrans_kernel<<<dim3(DIMS / 32, DIMS / 32, 2), 256>>>(Wq, Wk);
    mt_kernel<<<dim3(DIMS / BN, DIMS / BM), 256, SM_P3>>>();
    tv_kernel<<<dim3(2 * (DIMS / BN), MTOT / BM), 256, SM_P3>>>();
    scores_kernel<<<dim3(NTRI, 1, BATCH), 256, SM_P3>>>();
    softmax_kernel<<<dim3(MTOT), 256>>>();
    av_kernel<<<dim3(DIMS / BN, SEQ / BM, BATCH), 256, SM_P1>>>(O);
}